// round 1
// baseline (speedup 1.0000x reference)
#include <cuda_runtime.h>
#include <math.h>

// Problem constants
constexpr int S = 4;
constexpr int V = 2;
constexpr int B = 8192;
constexpr int D = 512;
constexpr int KV = S * V;          // 8 vectors per batch element
constexpr int NPAIR = KV * (KV + 1) / 2;  // 36 upper-triangle entries
constexpr float TEMP_INV = 10.0f;  // 1 / 0.1

constexpr int WARPS_PER_BLOCK = 8;
constexpr int THREADS = WARPS_PER_BLOCK * 32;
constexpr int NBLOCKS = B / WARPS_PER_BLOCK;  // 1024

// Deterministic two-stage reduction scratch (allocation-free)
__device__ float g_partials[NBLOCKS];

__host__ __device__ constexpr int TRI(int p, int q) {
    // upper-triangle index, p <= q
    return p * KV + q - p * (p + 1) / 2;
}

__global__ void __launch_bounds__(THREADS)
gram_loss_kernel(const float* __restrict__ views) {
    const int warp = threadIdx.x >> 5;
    const int lane = threadIdx.x & 31;
    const int b = blockIdx.x * WARPS_PER_BLOCK + warp;

    // Base pointers for the 8 vectors of this batch element.
    const float4* base[KV];
#pragma unroll
    for (int k = 0; k < KV; k++)
        base[k] = reinterpret_cast<const float4*>(views + ((size_t)k * B + b) * (size_t)D);

    float acc[NPAIR];
#pragma unroll
    for (int i = 0; i < NPAIR; i++) acc[i] = 0.0f;

    // D=512 floats = 128 float4 per vector; 32 lanes -> 4 chunks.
    // Lane loads float4 index (c*32 + lane): consecutive lanes contiguous -> coalesced.
#pragma unroll
    for (int c = 0; c < 4; c++) {
        float4 v[KV];
#pragma unroll
        for (int k = 0; k < KV; k++)
            v[k] = __ldg(&base[k][c * 32 + lane]);
#pragma unroll
        for (int p = 0; p < KV; p++) {
#pragma unroll
            for (int q = p; q < KV; q++) {
                float s = acc[TRI(p, q)];
                s = fmaf(v[p].x, v[q].x, s);
                s = fmaf(v[p].y, v[q].y, s);
                s = fmaf(v[p].z, v[q].z, s);
                s = fmaf(v[p].w, v[q].w, s);
                acc[TRI(p, q)] = s;
            }
        }
    }

    // Warp butterfly reduce all 36 partials
#pragma unroll
    for (int off = 16; off >= 1; off >>= 1) {
#pragma unroll
        for (int i = 0; i < NPAIR; i++)
            acc[i] += __shfl_xor_sync(0xffffffffu, acc[i], off);
    }

    __shared__ float warp_loss[WARPS_PER_BLOCK];

    if (lane == 0) {
        // Inverse norms (clamped like the reference: maximum(norm, 1e-12))
        float invn[KV];
#pragma unroll
        for (int k = 0; k < KV; k++)
            invn[k] = 1.0f / fmaxf(sqrtf(acc[TRI(k, k)]), 1e-12f);

        float loss = 0.0f;
#pragma unroll
        for (int i = 0; i < S; i++) {
            const int a = i * 2;  // anchor = (s=i, v=0)
            float l[1 + 2 * (S - 1)];  // 7 finite logits
            int cnt = 0;
            // positive: (i,0) . (i,1)
            l[cnt++] = acc[TRI(a, a + 1)] * invn[a] * invn[a + 1] * TEMP_INV;
            // negatives: (i,0) . (j,v) for j != i  (j==i rows are -inf, dropped)
#pragma unroll
            for (int j = 0; j < S; j++) {
                if (j == i) continue;
#pragma unroll
                for (int v2 = 0; v2 < V; v2++) {
                    const int jk = j * 2 + v2;
                    const int p = a < jk ? a : jk;
                    const int q = a < jk ? jk : a;
                    l[cnt++] = acc[TRI(p, q)] * invn[a] * invn[jk] * TEMP_INV;
                }
            }
            float m = l[0];
#pragma unroll
            for (int t = 1; t < 7; t++) m = fmaxf(m, l[t]);
            float se = 0.0f;
#pragma unroll
            for (int t = 0; t < 7; t++) se += __expf(l[t] - m);
            loss += m + __logf(se) - l[0];  // logsumexp - positive logit
        }
        warp_loss[warp] = loss;
    }
    __syncthreads();

    if (threadIdx.x == 0) {
        float s = 0.0f;
#pragma unroll
        for (int w = 0; w < WARPS_PER_BLOCK; w++) s += warp_loss[w];
        g_partials[blockIdx.x] = s;
    }
}

__global__ void __launch_bounds__(256)
final_reduce_kernel(float* __restrict__ out) {
    __shared__ float sm[256];
    float s = 0.0f;
    for (int i = threadIdx.x; i < NBLOCKS; i += 256) s += g_partials[i];
    sm[threadIdx.x] = s;
    __syncthreads();
#pragma unroll
    for (int stride = 128; stride >= 1; stride >>= 1) {
        if (threadIdx.x < stride) sm[threadIdx.x] += sm[threadIdx.x + stride];
        __syncthreads();
    }
    if (threadIdx.x == 0) out[0] = sm[0] / (float)(S * B);
}

extern "C" void kernel_launch(void* const* d_in, const int* in_sizes, int n_in,
                              void* d_out, int out_size) {
    const float* views = (const float*)d_in[0];
    float* out = (float*)d_out;
    gram_loss_kernel<<<NBLOCKS, THREADS>>>(views);
    final_reduce_kernel<<<1, 256>>>(out);
}